// round 10
// baseline (speedup 1.0000x reference)
#include <cuda_runtime.h>
#include <math.h>

#define NLEVELS 16
#define TBL (1 << 18)          // T = 2^18 entries per level
#define TMASK (TBL - 1)
#define PI2 2654435761u
#define THREADS 256
#define WARPS_PER_CTA (THREADS / 32)

#define BPTS (1 << 21)         // B = 2^21 points
#define NBINS (1 << 18)        // 512 x 512 Morton bins
#define SCAN_CTAS 256          // NBINS / 1024

struct Params {
    int ns[NLEVELS];
};

// ---- static scratch (no allocations allowed) ----
__device__ float4   g_rec[BPTS];       // permuted {x, y, idx_bits, pad}
__device__ unsigned g_hist[NBINS];     // local-exclusive offsets, then cursors
__device__ unsigned g_bsum[SCAN_CTAS]; // per-block exclusive offsets

// ---------------------------------------------------------------------------
__device__ __forceinline__ unsigned expand_bits(unsigned v) {
    v &= 0x1FF;
    v = (v | (v << 8)) & 0x00FF00FFu;
    v = (v | (v << 4)) & 0x0F0F0F0Fu;
    v = (v | (v << 2)) & 0x33333333u;
    v = (v | (v << 1)) & 0x55555555u;
    return v;
}

__device__ __forceinline__ unsigned morton_bin(float qx, float qy) {
    float x = fminf(fmaxf(qx, 0.0f), 1.0f);
    float y = fminf(fmaxf(qy, 0.0f), 1.0f);
    unsigned xb = min((unsigned)(x * 512.0f), 511u);
    unsigned yb = min((unsigned)(y * 512.0f), 511u);
    return (expand_bits(xb) << 1) | expand_bits(yb);
}

__device__ __forceinline__ unsigned warp_incl_scan(unsigned v) {
    #pragma unroll
    for (int off = 1; off < 32; off <<= 1) {
        unsigned t = __shfl_up_sync(0xFFFFFFFFu, v, off);
        if ((threadIdx.x & 31) >= off) v += t;
    }
    return v;
}

// ---- K0: zero histogram (vectorized) ----
__global__ void k_zero() {
    int i = blockIdx.x * blockDim.x + threadIdx.x;
    ((uint4*)g_hist)[i] = make_uint4(0, 0, 0, 0);
}

// ---- K1: histogram (2 points per thread) ----
__global__ void k_hist(const float4* __restrict__ xy2, int Bh) {
    int i = blockIdx.x * blockDim.x + threadIdx.x;
    if (i < Bh) {
        float4 q = xy2[i];
        atomicAdd(&g_hist[morton_bin(q.x, q.y)], 1u);
        atomicAdd(&g_hist[morton_bin(q.z, q.w)], 1u);
    }
}

// ---- K2: per-block exclusive scan (1024 bins per CTA) ----
__global__ __launch_bounds__(1024)
void k_scan1() {
    __shared__ unsigned wsum[32];
    int base = blockIdx.x * 1024;
    int lane = threadIdx.x & 31;
    int warp = threadIdx.x >> 5;

    unsigned v = g_hist[base + threadIdx.x];
    unsigned inc = warp_incl_scan(v);
    if (lane == 31) wsum[warp] = inc;
    __syncthreads();
    if (warp == 0) {
        unsigned s = wsum[lane];
        s = warp_incl_scan(s);
        wsum[lane] = s;
    }
    __syncthreads();
    unsigned woff = (warp > 0) ? wsum[warp - 1] : 0u;
    g_hist[base + threadIdx.x] = woff + inc - v;     // local exclusive
    if (threadIdx.x == 1023) g_bsum[blockIdx.x] = woff + inc;
}

// ---- K3: scan block totals (single CTA of 256) ----
__global__ __launch_bounds__(SCAN_CTAS)
void k_scan2() {
    __shared__ unsigned wsum[8];
    int lane = threadIdx.x & 31;
    int warp = threadIdx.x >> 5;

    unsigned v = g_bsum[threadIdx.x];
    unsigned inc = warp_incl_scan(v);
    if (lane == 31) wsum[warp] = inc;
    __syncthreads();
    if (threadIdx.x < 8) {
        unsigned s = wsum[threadIdx.x];
        #pragma unroll
        for (int off = 1; off < 8; off <<= 1) {
            unsigned t = __shfl_up_sync(0xFFu, s, off);
            if (threadIdx.x >= off) s += t;
        }
        wsum[threadIdx.x] = s;
    }
    __syncthreads();
    unsigned woff = (warp > 0) ? wsum[warp - 1] : 0u;
    g_bsum[threadIdx.x] = woff + inc - v;            // exclusive
}

// ---- K4: scatter (2 points per thread, block offset fused) ----
__global__ void k_scatter(const float4* __restrict__ xy2, int Bh) {
    int i = blockIdx.x * blockDim.x + threadIdx.x;
    if (i >= Bh) return;
    float4 q = xy2[i];
    {
        unsigned bin = morton_bin(q.x, q.y);
        unsigned p = atomicAdd(&g_hist[bin], 1u) + g_bsum[bin >> 10];
        g_rec[p] = make_float4(q.x, q.y, __int_as_float(2 * i), 0.0f);
    }
    {
        unsigned bin = morton_bin(q.z, q.w);
        unsigned p = atomicAdd(&g_hist[bin], 1u) + g_bsum[bin >> 10];
        g_rec[p] = make_float4(q.z, q.w, __int_as_float(2 * i + 1), 0.0f);
    }
}

// ---- K5: encode (R8 configuration). Lane = 4*p + g owns levels [4g, 4g+4)
//      of point p. Warp handles 8 points per pass, 4 passes = 32 points.
//      Hashed levels exploit XOR-adjacency: when x0 is even,
//      i10 = i00 ^ 1 -> both x-corners live in one 16B float4.
__global__ __launch_bounds__(THREADS)
void hash_enc_kernel(float* __restrict__ out,
                     const float2* __restrict__ tables,
                     int B, Params P)
{
    const int lane = threadIdx.x & 31;
    const int warp = threadIdx.x >> 5;
    const int g    = lane & 3;        // level group
    const int p8   = lane >> 2;       // point slot within pass (0..7)
    const int wbase = (blockIdx.x * WARPS_PER_CTA + warp) * 32;

    // per-lane level constants (levels 4g..4g+3)
    int   Nlv[4];
    float Nfv[4];
    #pragma unroll
    for (int j = 0; j < 4; ++j) {
        int n0 = P.ns[j], n1 = P.ns[4 + j], n2 = P.ns[8 + j], n3 = P.ns[12 + j];
        int nl = (g == 0) ? n0 : (g == 1) ? n1 : (g == 2) ? n2 : n3;
        Nlv[j] = nl;
        Nfv[j] = (float)nl;
    }

    #pragma unroll
    for (int pass = 0; pass < 4; ++pass) {
        int pi = wbase + pass * 8 + p8;      // sorted point index
        if (pi >= B) continue;

        float4 rec = g_rec[pi];              // 4 lanes share each 16B record
        int row = __float_as_int(rec.z);

        float x = fminf(fmaxf(rec.x, 0.0f), 1.0f);
        float y = fminf(fmaxf(rec.y, 0.0f), 1.0f);

        float rr[8];

        #pragma unroll
        for (int j = 0; j < 4; ++j) {
            const int   Nl = Nlv[j];
            const float Nf = Nfv[j];

            float px = x * Nf;
            float py = y * Nf;
            float fx0 = floorf(px);
            float fy0 = floorf(py);
            float wx = px - fx0;
            float wy = py - fy0;

            int x0 = (int)fx0;
            int y0 = (int)fy0;
            int x1 = min(x0 + 1, Nl);
            int y1 = min(y0 + 1, Nl);

            const float2* tab = tables + ((size_t)(g * 4 + j)) * TBL;
            float2 f00, f10, f01, f11;

            if (Nl > 511) {
                // hashed: idx = (xi ^ yi*PI2) & TMASK (congruent to the
                // reference's int64 math since 2^18 | 2^32).
                unsigned hy0 = (unsigned)y0 * PI2;
                unsigned hy1 = (unsigned)y1 * PI2;
                unsigned i00 = ((unsigned)x0 ^ hy0) & TMASK;
                unsigned i10 = ((unsigned)x1 ^ hy0) & TMASK;
                unsigned i01 = ((unsigned)x0 ^ hy1) & TMASK;
                unsigned i11 = ((unsigned)x1 ^ hy1) & TMASK;

                const float4* t4 = (const float4*)tab;
                float4 a0 = __ldg(t4 + (i00 >> 1));   // entries {i00&~1, |1}
                float4 a1 = __ldg(t4 + (i01 >> 1));
                bool hi0 = (i00 & 1u);
                bool hi1 = (i01 & 1u);
                f00 = hi0 ? make_float2(a0.z, a0.w) : make_float2(a0.x, a0.y);
                f01 = hi1 ? make_float2(a1.z, a1.w) : make_float2(a1.x, a1.y);

                // paired: x0 even and not clamped -> i10 == i00^1 (same float4)
                bool paired = ((x0 & 1) == 0) && (x1 == x0 + 1);
                if (paired) {
                    f10 = hi0 ? make_float2(a0.x, a0.y) : make_float2(a0.z, a0.w);
                    f11 = hi1 ? make_float2(a1.x, a1.y) : make_float2(a1.z, a1.w);
                } else {
                    f10 = __ldg(tab + i10);
                    f11 = __ldg(tab + i11);
                }
            } else {
                // dense: idx = xi*(Nl+1)+yi  (levels 0..5, L1-resident)
                unsigned stride = (unsigned)(Nl + 1);
                f00 = __ldg(tab + ((unsigned)x0 * stride + (unsigned)y0));
                f10 = __ldg(tab + ((unsigned)x1 * stride + (unsigned)y0));
                f01 = __ldg(tab + ((unsigned)x0 * stride + (unsigned)y1));
                f11 = __ldg(tab + ((unsigned)x1 * stride + (unsigned)y1));
            }

            float w00 = (1.0f - wx) * (1.0f - wy);
            float w10 = wx * (1.0f - wy);
            float w01 = (1.0f - wx) * wy;
            float w11 = wx * wy;

            rr[2*j]   = f00.x * w00 + f10.x * w10 + f01.x * w01 + f11.x * w11;
            rr[2*j+1] = f00.y * w00 + f10.y * w10 + f01.y * w01 + f11.y * w11;
        }

        // lane's 8 floats are contiguous: out[row*32 + 8g .. 8g+8)
        float* orow = out + (size_t)row * (2 * NLEVELS) + g * 8;
        ((float4*)orow)[0] = make_float4(rr[0], rr[1], rr[2], rr[3]);
        ((float4*)orow)[1] = make_float4(rr[4], rr[5], rr[6], rr[7]);
    }
}

// ---------------------------------------------------------------------------
extern "C" void kernel_launch(void* const* d_in, const int* in_sizes, int n_in,
                              void* d_out, int out_size)
{
    const float4* xy2    = (const float4*)d_in[0];   // 2 points per float4
    const float2* tables = (const float2*)d_in[1];
    float* out           = (float*)d_out;

    int B = in_sizes[0] / 2;
    int Bh = B / 2;                                  // B = 2^21, even

    // Replicate the reference's NS computation with identical double-precision
    // libm calls so floor() decisions match bit-for-bit.
    Params P;
    double b = exp((log(131072.0) - log(16.0)) / 15.0);
    for (int l = 0; l < NLEVELS; ++l) {
        P.ns[l] = (int)floor(16.0 * pow(b, (double)l));
    }

    int hblocks = (Bh + THREADS - 1) / THREADS;
    int pblocks = (B + THREADS - 1) / THREADS;

    k_zero   <<<NBINS / 4 / 256, 256>>>();
    k_hist   <<<hblocks, THREADS>>>(xy2, Bh);
    k_scan1  <<<SCAN_CTAS, 1024>>>();
    k_scan2  <<<1, SCAN_CTAS>>>();
    k_scatter<<<hblocks, THREADS>>>(xy2, Bh);
    hash_enc_kernel<<<pblocks, THREADS>>>(out, tables, B, P);
}

// round 11
// speedup vs baseline: 1.5310x; 1.5310x over previous
#include <cuda_runtime.h>
#include <math.h>

#define NLEVELS 16
#define TBL (1 << 18)          // T = 2^18 entries per level
#define TMASK (TBL - 1)
#define PI2 2654435761u
#define THREADS 256
#define WARPS_PER_CTA (THREADS / 32)

#define BPTS (1 << 21)         // B = 2^21 points
#define NBINS (1 << 18)        // 512 x 512 Morton bins
#define SCAN_CTAS 256          // NBINS / 1024

struct Params {
    int ns[NLEVELS];
};

// ---- static scratch (no allocations allowed) ----
__device__ float4   g_rec[BPTS];       // permuted {x, y, idx_bits, pad}
__device__ unsigned g_hist[NBINS];     // local-exclusive offsets, then cursors
__device__ unsigned g_bsum[SCAN_CTAS]; // per-block exclusive offsets

// ---------------------------------------------------------------------------
__device__ __forceinline__ unsigned expand_bits(unsigned v) {
    v &= 0x1FF;
    v = (v | (v << 8)) & 0x00FF00FFu;
    v = (v | (v << 4)) & 0x0F0F0F0Fu;
    v = (v | (v << 2)) & 0x33333333u;
    v = (v | (v << 1)) & 0x55555555u;
    return v;
}

__device__ __forceinline__ unsigned morton_bin(float qx, float qy) {
    float x = fminf(fmaxf(qx, 0.0f), 1.0f);
    float y = fminf(fmaxf(qy, 0.0f), 1.0f);
    unsigned xb = min((unsigned)(x * 512.0f), 511u);
    unsigned yb = min((unsigned)(y * 512.0f), 511u);
    return (expand_bits(xb) << 1) | expand_bits(yb);
}

__device__ __forceinline__ unsigned warp_incl_scan(unsigned v) {
    #pragma unroll
    for (int off = 1; off < 32; off <<= 1) {
        unsigned t = __shfl_up_sync(0xFFFFFFFFu, v, off);
        if ((threadIdx.x & 31) >= off) v += t;
    }
    return v;
}

// ---- K0: zero histogram (vectorized) ----
__global__ void k_zero() {
    int i = blockIdx.x * blockDim.x + threadIdx.x;
    ((uint4*)g_hist)[i] = make_uint4(0, 0, 0, 0);
}

// ---- K1: histogram (2 points per thread) ----
__global__ void k_hist(const float4* __restrict__ xy2, int Bh) {
    int i = blockIdx.x * blockDim.x + threadIdx.x;
    if (i < Bh) {
        float4 q = xy2[i];
        atomicAdd(&g_hist[morton_bin(q.x, q.y)], 1u);
        atomicAdd(&g_hist[morton_bin(q.z, q.w)], 1u);
    }
}

// ---- K2: per-block exclusive scan (1024 bins per CTA) ----
__global__ __launch_bounds__(1024)
void k_scan1() {
    __shared__ unsigned wsum[32];
    int base = blockIdx.x * 1024;
    int lane = threadIdx.x & 31;
    int warp = threadIdx.x >> 5;

    unsigned v = g_hist[base + threadIdx.x];
    unsigned inc = warp_incl_scan(v);
    if (lane == 31) wsum[warp] = inc;
    __syncthreads();
    if (warp == 0) {
        unsigned s = wsum[lane];
        s = warp_incl_scan(s);
        wsum[lane] = s;
    }
    __syncthreads();
    unsigned woff = (warp > 0) ? wsum[warp - 1] : 0u;
    g_hist[base + threadIdx.x] = woff + inc - v;     // local exclusive
    if (threadIdx.x == 1023) g_bsum[blockIdx.x] = woff + inc;
}

// ---- K3: scan block totals (single CTA of 256) ----
__global__ __launch_bounds__(SCAN_CTAS)
void k_scan2() {
    __shared__ unsigned wsum[8];
    int lane = threadIdx.x & 31;
    int warp = threadIdx.x >> 5;

    unsigned v = g_bsum[threadIdx.x];
    unsigned inc = warp_incl_scan(v);
    if (lane == 31) wsum[warp] = inc;
    __syncthreads();
    if (threadIdx.x < 8) {
        unsigned s = wsum[threadIdx.x];
        #pragma unroll
        for (int off = 1; off < 8; off <<= 1) {
            unsigned t = __shfl_up_sync(0xFFu, s, off);
            if (threadIdx.x >= off) s += t;
        }
        wsum[threadIdx.x] = s;
    }
    __syncthreads();
    unsigned woff = (warp > 0) ? wsum[warp - 1] : 0u;
    g_bsum[threadIdx.x] = woff + inc - v;            // exclusive
}

// ---- K4: scatter (2 points per thread, block offset fused) ----
__global__ void k_scatter(const float4* __restrict__ xy2, int Bh) {
    int i = blockIdx.x * blockDim.x + threadIdx.x;
    if (i >= Bh) return;
    float4 q = xy2[i];
    {
        unsigned bin = morton_bin(q.x, q.y);
        unsigned p = atomicAdd(&g_hist[bin], 1u) + g_bsum[bin >> 10];
        g_rec[p] = make_float4(q.x, q.y, __int_as_float(2 * i), 0.0f);
    }
    {
        unsigned bin = morton_bin(q.z, q.w);
        unsigned p = atomicAdd(&g_hist[bin], 1u) + g_bsum[bin >> 10];
        g_rec[p] = make_float4(q.z, q.w, __int_as_float(2 * i + 1), 0.0f);
    }
}

// ---- K5: encode (R8 configuration). Lane = 4*p + g owns levels [4g, 4g+4)
//      of point p. Warp handles 8 points per pass, 4 passes = 32 points.
//      Hashed levels exploit XOR-adjacency: when x0 is even,
//      i10 = i00 ^ 1 -> both x-corners live in one 16B float4.
__global__ __launch_bounds__(THREADS)
void hash_enc_kernel(float* __restrict__ out,
                     const float2* __restrict__ tables,
                     int B, Params P)
{
    const int lane = threadIdx.x & 31;
    const int warp = threadIdx.x >> 5;
    const int g    = lane & 3;        // level group
    const int p8   = lane >> 2;       // point slot within pass (0..7)
    const int wbase = (blockIdx.x * WARPS_PER_CTA + warp) * 32;

    // per-lane level constants (levels 4g..4g+3)
    int   Nlv[4];
    float Nfv[4];
    #pragma unroll
    for (int j = 0; j < 4; ++j) {
        int n0 = P.ns[j], n1 = P.ns[4 + j], n2 = P.ns[8 + j], n3 = P.ns[12 + j];
        int nl = (g == 0) ? n0 : (g == 1) ? n1 : (g == 2) ? n2 : n3;
        Nlv[j] = nl;
        Nfv[j] = (float)nl;
    }

    #pragma unroll
    for (int pass = 0; pass < 4; ++pass) {
        int pi = wbase + pass * 8 + p8;      // sorted point index
        if (pi >= B) continue;

        float4 rec = g_rec[pi];              // 4 lanes share each 16B record
        int row = __float_as_int(rec.z);

        float x = fminf(fmaxf(rec.x, 0.0f), 1.0f);
        float y = fminf(fmaxf(rec.y, 0.0f), 1.0f);

        float rr[8];

        #pragma unroll
        for (int j = 0; j < 4; ++j) {
            const int   Nl = Nlv[j];
            const float Nf = Nfv[j];

            float px = x * Nf;
            float py = y * Nf;
            float fx0 = floorf(px);
            float fy0 = floorf(py);
            float wx = px - fx0;
            float wy = py - fy0;

            int x0 = (int)fx0;
            int y0 = (int)fy0;
            int x1 = min(x0 + 1, Nl);
            int y1 = min(y0 + 1, Nl);

            const float2* tab = tables + ((size_t)(g * 4 + j)) * TBL;
            float2 f00, f10, f01, f11;

            if (Nl > 511) {
                // hashed: idx = (xi ^ yi*PI2) & TMASK (congruent to the
                // reference's int64 math since 2^18 | 2^32).
                unsigned hy0 = (unsigned)y0 * PI2;
                unsigned hy1 = (unsigned)y1 * PI2;
                unsigned i00 = ((unsigned)x0 ^ hy0) & TMASK;
                unsigned i10 = ((unsigned)x1 ^ hy0) & TMASK;
                unsigned i01 = ((unsigned)x0 ^ hy1) & TMASK;
                unsigned i11 = ((unsigned)x1 ^ hy1) & TMASK;

                const float4* t4 = (const float4*)tab;
                float4 a0 = __ldg(t4 + (i00 >> 1));   // entries {i00&~1, |1}
                float4 a1 = __ldg(t4 + (i01 >> 1));
                bool hi0 = (i00 & 1u);
                bool hi1 = (i01 & 1u);
                f00 = hi0 ? make_float2(a0.z, a0.w) : make_float2(a0.x, a0.y);
                f01 = hi1 ? make_float2(a1.z, a1.w) : make_float2(a1.x, a1.y);

                // paired: x0 even and not clamped -> i10 == i00^1 (same float4)
                bool paired = ((x0 & 1) == 0) && (x1 == x0 + 1);
                if (paired) {
                    f10 = hi0 ? make_float2(a0.x, a0.y) : make_float2(a0.z, a0.w);
                    f11 = hi1 ? make_float2(a1.x, a1.y) : make_float2(a1.z, a1.w);
                } else {
                    f10 = __ldg(tab + i10);
                    f11 = __ldg(tab + i11);
                }
            } else {
                // dense: idx = xi*(Nl+1)+yi  (levels 0..5, L1-resident)
                unsigned stride = (unsigned)(Nl + 1);
                f00 = __ldg(tab + ((unsigned)x0 * stride + (unsigned)y0));
                f10 = __ldg(tab + ((unsigned)x1 * stride + (unsigned)y0));
                f01 = __ldg(tab + ((unsigned)x0 * stride + (unsigned)y1));
                f11 = __ldg(tab + ((unsigned)x1 * stride + (unsigned)y1));
            }

            float w00 = (1.0f - wx) * (1.0f - wy);
            float w10 = wx * (1.0f - wy);
            float w01 = (1.0f - wx) * wy;
            float w11 = wx * wy;

            rr[2*j]   = f00.x * w00 + f10.x * w10 + f01.x * w01 + f11.x * w11;
            rr[2*j+1] = f00.y * w00 + f10.y * w10 + f01.y * w01 + f11.y * w11;
        }

        // lane's 8 floats are contiguous: out[row*32 + 8g .. 8g+8)
        float* orow = out + (size_t)row * (2 * NLEVELS) + g * 8;
        ((float4*)orow)[0] = make_float4(rr[0], rr[1], rr[2], rr[3]);
        ((float4*)orow)[1] = make_float4(rr[4], rr[5], rr[6], rr[7]);
    }
}

// ---------------------------------------------------------------------------
extern "C" void kernel_launch(void* const* d_in, const int* in_sizes, int n_in,
                              void* d_out, int out_size)
{
    const float4* xy2    = (const float4*)d_in[0];   // 2 points per float4
    const float2* tables = (const float2*)d_in[1];
    float* out           = (float*)d_out;

    int B = in_sizes[0] / 2;
    int Bh = B / 2;                                  // B = 2^21, even

    // Replicate the reference's NS computation with identical double-precision
    // libm calls so floor() decisions match bit-for-bit.
    Params P;
    double b = exp((log(131072.0) - log(16.0)) / 15.0);
    for (int l = 0; l < NLEVELS; ++l) {
        P.ns[l] = (int)floor(16.0 * pow(b, (double)l));
    }

    int hblocks = (Bh + THREADS - 1) / THREADS;
    int pblocks = (B + THREADS - 1) / THREADS;

    k_zero   <<<NBINS / 4 / 256, 256>>>();
    k_hist   <<<hblocks, THREADS>>>(xy2, Bh);
    k_scan1  <<<SCAN_CTAS, 1024>>>();
    k_scan2  <<<1, SCAN_CTAS>>>();
    k_scatter<<<hblocks, THREADS>>>(xy2, Bh);
    hash_enc_kernel<<<pblocks, THREADS>>>(out, tables, B, P);
}